// round 5
// baseline (speedup 1.0000x reference)
#include <cuda_runtime.h>
#include <cuda_bf16.h>
#include <stdint.h>
#include <math.h>

// ---------------- global scratch (no allocations allowed) ----------------
// g_Md2: [n=256][o=128] fp32 M^T, then d[256] at offset 32768. Zeroed by memset node.
__device__ __align__(16) float g_Md2[256 * 128 + 256];
__device__ unsigned g_cnt = 0;     // barrier arrival counter (returns to 0 every launch)
__device__ unsigned g_sense = 0;   // barrier sense (toggles every launch)

// ---------------- helpers ----------------
__device__ __forceinline__ void hilo(float2 f, uint32_t& h, uint32_t& l) {
    __nv_bfloat16 ax = __float2bfloat16(f.x), ay = __float2bfloat16(f.y);
    __nv_bfloat162 hv; hv.x = ax; hv.y = ay;
    float rx = f.x - __bfloat162float(ax);
    float ry = f.y - __bfloat162float(ay);
    __nv_bfloat162 lv = __floats2bfloat162_rn(rx, ry);
    h = *reinterpret_cast<uint32_t*>(&hv);
    l = *reinterpret_cast<uint32_t*>(&lv);
}

__device__ __forceinline__ void mma16816(float* c, const uint32_t* a, uint32_t b0, uint32_t b1) {
    asm volatile(
        "mma.sync.aligned.m16n8k16.row.col.f32.bf16.bf16.f32 "
        "{%0,%1,%2,%3}, {%4,%5,%6,%7}, {%8,%9}, {%0,%1,%2,%3};\n"
        : "+f"(c[0]), "+f"(c[1]), "+f"(c[2]), "+f"(c[3])
        : "r"(a[0]), "r"(a[1]), "r"(a[2]), "r"(a[3]), "r"(b0), "r"(b1));
}

// SMEM byte offsets (dynamic, 162.4 KB total)
static constexpr int SO_BFR  = 0;        // uint4 [Tg=32][s=8][lane=32]         = 131072 B
static constexpr int SO_AFR  = 131072;   // uint4 [wm2mt=4][s=8][lane=32][2]    =  32768 B
static constexpr int SO_C8   = 163840;   // float[256]
static constexpr int SO_DS   = 164864;   // float[256]
static constexpr int SO_ALS  = 165888;   // float[64]
static constexpr int SO_LUT  = 166144;   // float[16]
static constexpr int SMEM_TOTAL = 166208;
// phase-A overlay (inside [0,131072)):
static constexpr int SO_SA   = 0;        // float[129][68] = 35088 B
static constexpr int SO_SW   = 36864;    // float[64][16]  =  4096 B
static constexpr int SO_S16  = 40960;    // float[16][64]  =  4096 B

__global__ __launch_bounds__(256, 1) void fused_all(
    const float* __restrict__ x,        // (8192,128)
    const int*   __restrict__ opt,      // (8192,)
    const float* __restrict__ A,        // pre_fc_w (128,512)
    const float* __restrict__ bias,     // pre_fc_b (512,)
    const float* __restrict__ vw,       // value_w (512,1024)
    const float* __restrict__ vb,       // value_b (1024,)
    const float* __restrict__ pw,       // p_w (16,64)
    const float* __restrict__ pb,       // p_b (64,)
    float* __restrict__ out)            // (8192,256)
{
    extern __shared__ __align__(16) char smem[];
    int tid = threadIdx.x;
    int cta = blockIdx.x;               // 0..127
    int m0 = cta * 64;

    // =============== Phase A: partial M^T & d, alpha LUT, c8 ===============
    // CTA (ks = cta>>4, nt = cta&15): k-slice 64 wide, n-slice 16 wide, all 129 o-rows.
    {
        float* sA  = (float*)(smem + SO_SA);    // [129][68]
        float* sW  = (float*)(smem + SO_SW);    // [64][16]
        float* s16 = (float*)(smem + SO_S16);   // [16][64]
        float* lut = (float*)(smem + SO_LUT);
        float* c8s = (float*)(smem + SO_C8);

        int ks = cta >> 4, nt = cta & 15;
        int k0 = ks * 64, n0 = nt * 16;

        // stage sA (129 x 64)
        for (int idx = tid; idx < 129 * 64; idx += 256) {
            int o = idx >> 6, k = idx & 63;
            sA[o * 68 + k] = (o < 128) ? A[o * 512 + k0 + k] : bias[k0 + k];
        }
        // stage sW (64 x 16), head-mean folded
        #pragma unroll
        for (int i = 0; i < 4; i++) {
            int idx = tid + i * 256;
            int k = idx >> 4, j = idx & 15;
            const float* p = vw + (size_t)(k0 + k) * 1024 + n0 + j;
            sW[k * 16 + j] = 0.25f * (p[0] + p[256] + p[512] + p[768]);
        }
        // stage p-scores + c8 (both independent of barrier)
        for (int i = tid; i < 16 * 64; i += 256) s16[i] = pw[i] + pb[i & 63];
        {
            float c = 0.25f * (vb[tid] + vb[tid + 256] + vb[tid + 512] + vb[tid + 768]);
            c8s[tid] = 0.125f * c;
        }
        __syncthreads();

        // M-partial: thread (j = n_local, r = o-phase)
        int j = tid & 15, r = tid >> 4;
        float w[64];
        #pragma unroll
        for (int k = 0; k < 64; k++) w[k] = sW[k * 16 + j];
        for (int o = r; o < 129; o += 16) {
            float acc = 0.f;
            #pragma unroll 16
            for (int k = 0; k < 64; k++) acc += sA[o * 68 + k] * w[k];
            int n = n0 + j;
            if (o < 128) atomicAdd(&g_Md2[n * 128 + o], acc);
            else         atomicAdd(&g_Md2[32768 + n], acc);
        }

        // alpha LUT (threads 0..15)
        if (tid < 16) {
            float* s = s16 + tid * 64;
            float S = 0.f;
            for (int t8 = 0; t8 < 8; t8++) {
                float bv = -1e30f; int bi = 0;
                for (int n = 0; n < 64; n++) {
                    float v = s[n];
                    if (v > bv) { bv = v; bi = n; }
                }
                S += 1.f / (1.f + expf(-bv));   // softmax([x,0])[0] = sigmoid(x)
                s[bi] = -1e30f;
            }
            lut[tid] = S * (1.0f / 64.0f);
        }
    }

    // =============== Grid barrier (sense-reversing, replay-safe) ===============
    __syncthreads();
    if (tid == 0) {
        unsigned old = *(volatile unsigned*)&g_sense;
        __threadfence();
        unsigned t = atomicAdd(&g_cnt, 1u);
        if (t == gridDim.x - 1) {
            atomicExch(&g_cnt, 0u);
            __threadfence();
            atomicExch(&g_sense, old ^ 1u);
        } else {
            while (*(volatile unsigned*)&g_sense == old) { }
        }
        __threadfence();
    }
    __syncthreads();

    // =============== Phase C: fragment build + HMMA GEMM + epilogue ===============
    uint4* bfrs = (uint4*)(smem + SO_BFR);
    uint4* afrs = (uint4*)(smem + SO_AFR);
    float* c8s  = (float*)(smem + SO_C8);
    float* ds   = (float*)(smem + SO_DS);
    float* als  = (float*)(smem + SO_ALS);
    float* lut  = (float*)(smem + SO_LUT);

    ds[tid] = __ldcg(&g_Md2[32768 + tid]);
    if (tid < 64) als[tid] = lut[opt[m0 + tid]];

    // B fragments: [Tg][s][lane] -> {b0_hi, b1_hi, b0_lo, b1_lo}
    #pragma unroll 4
    for (int i = 0; i < 32; i++) {
        int p = tid + i * 256;                  // 0..8191
        int lane_ = p & 31, s = (p >> 5) & 7, Tg = p >> 8;
        int n = Tg * 8 + (lane_ >> 2);
        int k0 = s * 16 + (lane_ & 3) * 2;
        const float2* mp = (const float2*)&g_Md2[n * 128 + k0];
        float2 f0 = __ldcg(mp);
        float2 f1 = __ldcg(mp + 4);             // +8 floats
        uint4 q; uint32_t l0, l1;
        hilo(f0, q.x, l0); hilo(f1, q.y, l1);
        q.z = l0; q.w = l1;
        bfrs[p] = q;
    }

    // A fragments: [wm][mt][s][lane] -> hi uint4, lo uint4
    #pragma unroll
    for (int i = 0; i < 4; i++) {
        int p = tid + i * 256;                  // 0..1023
        int lane_ = p & 31, s = (p >> 5) & 7, mt = (p >> 8) & 1, wm_ = p >> 9;
        int row = m0 + wm_ * 32 + mt * 16 + (lane_ >> 2);
        int k0 = s * 16 + (lane_ & 3) * 2;
        float2 xa = *(const float2*)&x[(size_t)row * 128 + k0];
        float2 xb = *(const float2*)&x[(size_t)(row + 8) * 128 + k0];
        float2 xc = *(const float2*)&x[(size_t)row * 128 + k0 + 8];
        float2 xd = *(const float2*)&x[(size_t)(row + 8) * 128 + k0 + 8];
        uint4 hi, lo;
        hilo(xa, hi.x, lo.x); hilo(xb, hi.y, lo.y);
        hilo(xc, hi.z, lo.z); hilo(xd, hi.w, lo.w);
        afrs[p * 2]     = hi;
        afrs[p * 2 + 1] = lo;
    }
    __syncthreads();

    // GEMM: warp (wm = wid&1 -> 32 rows, wn = wid>>1 -> 64 cols)
    int wid = tid >> 5, lane = tid & 31;
    int wm = wid & 1, wn = wid >> 1;
    float acc[2][8][4];
    #pragma unroll
    for (int a_ = 0; a_ < 2; a_++)
        #pragma unroll
        for (int b_ = 0; b_ < 8; b_++)
            #pragma unroll
            for (int c_ = 0; c_ < 4; c_++) acc[a_][b_][c_] = 0.f;

    #pragma unroll
    for (int s = 0; s < 8; s++) {
        uint4 ah[2], al2[2];
        #pragma unroll
        for (int mt = 0; mt < 2; mt++) {
            int ai = (((wm * 2 + mt) * 8 + s) * 32 + lane) * 2;
            ah[mt]  = afrs[ai];
            al2[mt] = afrs[ai + 1];
        }
        #pragma unroll
        for (int T = 0; T < 8; T++) {
            uint4 bq = bfrs[((wn * 8 + T) * 8 + s) * 32 + lane];
            #pragma unroll
            for (int mt = 0; mt < 2; mt++) {
                mma16816(acc[mt][T], (const uint32_t*)&ah[mt],  bq.x, bq.y);  // hi*hi
                mma16816(acc[mt][T], (const uint32_t*)&ah[mt],  bq.z, bq.w);  // hi*lo
                mma16816(acc[mt][T], (const uint32_t*)&al2[mt], bq.x, bq.y);  // lo*hi
            }
        }
    }

    // epilogue: out = alpha[opt]*(acc + d[n]) + c8[n]
    int g = lane >> 2, tig = lane & 3;
    #pragma unroll
    for (int mt = 0; mt < 2; mt++) {
        int rl = wm * 32 + mt * 16 + g;
        float a1 = als[rl], a2 = als[rl + 8];
        size_t ro1 = (size_t)(m0 + rl) * 256;
        size_t ro2 = (size_t)(m0 + rl + 8) * 256;
        #pragma unroll
        for (int T = 0; T < 8; T++) {
            int n = wn * 64 + T * 8 + tig * 2;
            float dn0 = ds[n], dn1 = ds[n + 1];
            float cn0 = c8s[n], cn1 = c8s[n + 1];
            float* c = acc[mt][T];
            float2 o1 = { fmaf(c[0] + dn0, a1, cn0), fmaf(c[1] + dn1, a1, cn1) };
            float2 o2 = { fmaf(c[2] + dn0, a2, cn0), fmaf(c[3] + dn1, a2, cn1) };
            *(float2*)&out[ro1 + n] = o1;
            *(float2*)&out[ro2 + n] = o2;
        }
    }
}

extern "C" void kernel_launch(void* const* d_in, const int* in_sizes, int n_in,
                              void* d_out, int out_size) {
    const float* x        = (const float*)d_in[0];   // (8192,128)
    const int*   option   = (const int*)  d_in[1];   // (8192,)
    const float* pre_fc_w = (const float*)d_in[2];   // (128,512)
    const float* pre_fc_b = (const float*)d_in[3];   // (512,)
    const float* value_w  = (const float*)d_in[4];   // (512,1024)
    const float* value_b  = (const float*)d_in[5];   // (1024,)
    const float* p_w      = (const float*)d_in[6];   // (16,64)
    const float* p_b      = (const float*)d_in[7];   // (64,)
    float* out = (float*)d_out;                      // (8192,256)

    void* pMd = nullptr;
    cudaGetSymbolAddress(&pMd, g_Md2);
    cudaMemsetAsync(pMd, 0, (256 * 128 + 256) * sizeof(float));

    cudaFuncSetAttribute(fused_all, cudaFuncAttributeMaxDynamicSharedMemorySize, SMEM_TOTAL);
    fused_all<<<128, 256, SMEM_TOTAL>>>(x, option, pre_fc_w, pre_fc_b,
                                        value_w, value_b, p_w, p_b, out);
}

// round 6
// speedup vs baseline: 1.2295x; 1.2295x over previous
#include <cuda_runtime.h>
#include <cuda_bf16.h>
#include <stdint.h>
#include <math.h>

// ---------------- global scratch (no allocations allowed) ----------------
// B fragments for main GEMM: [Tg=32][s=8][lane=32] uint4 {b0_hi, b1_hi, b0_lo, b1_lo}
__device__ __align__(16) uint4 g_bfr[32 * 8 * 32];
__device__ __align__(16) float g_d[256];      // bias row of M
__device__ __align__(16) float g_c8[256];     // mean-over-heads value_b / 8
__device__ __align__(16) float g_alpha[16];   // per-option coefficient

// ---------------- helpers ----------------
__device__ __forceinline__ void hilo(float2 f, uint32_t& h, uint32_t& l) {
    __nv_bfloat16 ax = __float2bfloat16(f.x), ay = __float2bfloat16(f.y);
    __nv_bfloat162 hv; hv.x = ax; hv.y = ay;
    float rx = f.x - __bfloat162float(ax);
    float ry = f.y - __bfloat162float(ay);
    __nv_bfloat162 lv = __floats2bfloat162_rn(rx, ry);
    h = *reinterpret_cast<uint32_t*>(&hv);
    l = *reinterpret_cast<uint32_t*>(&lv);
}

__device__ __forceinline__ void mma16816(float* c, const uint32_t* a, uint32_t b0, uint32_t b1) {
    asm volatile(
        "mma.sync.aligned.m16n8k16.row.col.f32.bf16.bf16.f32 "
        "{%0,%1,%2,%3}, {%4,%5,%6,%7}, {%8,%9}, {%0,%1,%2,%3};\n"
        : "+f"(c[0]), "+f"(c[1]), "+f"(c[2]), "+f"(c[3])
        : "r"(a[0]), "r"(a[1]), "r"(a[2]), "r"(a[3]), "r"(b0), "r"(b1));
}

// ================= kernel 1: prep =================
// Blocks 0..63: n-slab of 4 columns, full K=512 (no atomics). Computes
// M^T[n][o] = sum_k foldW[k][n] * A_ext[o][k] (o=128 row -> d), packs bf16
// hi/lo B-fragments straight into g_bfr in mma lane order.
// Block 64: alpha LUT + c8.
static constexpr int P_SA  = 0;        // float[129][140] = 72240 B (LD=140: 16B-aligned rows, conflict-free)
static constexpr int P_SW  = 72240;    // float[128][4]   =  2048 B
static constexpr int P_SMT = 74288;    // float[4][140]   =  2240 B
static constexpr int P_SMEM = 76528;

__global__ __launch_bounds__(256) void prep(const float* __restrict__ A,    // pre_fc_w (128,512)
                                            const float* __restrict__ bias, // pre_fc_b (512,)
                                            const float* __restrict__ vw,   // value_w (512,1024)
                                            const float* __restrict__ pw,   // p_w (16,64)
                                            const float* __restrict__ pb,   // p_b (64,)
                                            const float* __restrict__ vb) { // value_b (1024,)
    extern __shared__ __align__(16) char sm[];
    int b = blockIdx.x, tid = threadIdx.x;

    if (b == 64) {
        float* s16 = (float*)sm;   // [16][64]
        float c = 0.25f * (vb[tid] + vb[tid + 256] + vb[tid + 512] + vb[tid + 768]);
        g_c8[tid] = 0.125f * c;
        for (int i = tid; i < 16 * 64; i += 256) s16[i] = pw[i] + pb[i & 63];
        __syncthreads();
        if (tid < 16) {
            float* s = s16 + tid * 64;
            float S = 0.f;
            for (int t8 = 0; t8 < 8; t8++) {
                float bv = -1e30f; int bi = 0;
                for (int n = 0; n < 64; n++) {
                    float v = s[n];
                    if (v > bv) { bv = v; bi = n; }
                }
                S += 1.f / (1.f + expf(-bv));   // softmax([x,0])[0] = sigmoid(x)
                s[bi] = -1e30f;
            }
            g_alpha[tid] = S * (1.0f / 64.0f);
        }
        return;
    }

    float* sA  = (float*)(sm + P_SA);    // [129][140]
    float* sW  = (float*)(sm + P_SW);    // [128][4]
    float* sMt = (float*)(sm + P_SMT);   // [4][140]
    int n0 = b * 4;
    int j = tid & 3, r = tid >> 2;       // j = local n, r = 0..63 (o rows r, r+64; r==0 also 128)
    float acc0 = 0.f, acc1 = 0.f, acc2 = 0.f;

    for (int kc = 0; kc < 4; kc++) {
        int k0 = kc * 128;
        if (kc) __syncthreads();
        // foldW slab (128 k x 4 n)
        #pragma unroll
        for (int i = 0; i < 2; i++) {
            int idx = tid + i * 256;
            int k = idx >> 2, jj = idx & 3;
            const float* p = vw + (size_t)(k0 + k) * 1024 + n0 + jj;
            sW[k * 4 + jj] = 0.25f * (p[0] + p[256] + p[512] + p[768]);
        }
        // A slab (129 rows x 128 k), float4
        #pragma unroll
        for (int i = 0; i < 17; i++) {
            int fid = tid + i * 256;
            if (fid < 129 * 32) {
                int row = fid >> 5, kq = fid & 31;
                float4 v = (row < 128) ? *(const float4*)(A + (size_t)row * 512 + k0 + kq * 4)
                                       : *(const float4*)(bias + k0 + kq * 4);
                *(float4*)(sA + row * 140 + kq * 4) = v;
            }
        }
        __syncthreads();
        #pragma unroll 16
        for (int k = 0; k < 128; k++) {
            float wv = sW[k * 4 + j];
            acc0 = fmaf(sA[r * 140 + k], wv, acc0);
            acc1 = fmaf(sA[(r + 64) * 140 + k], wv, acc1);
            if (r == 0) acc2 = fmaf(sA[128 * 140 + k], wv, acc2);
        }
    }
    sMt[j * 140 + r]      = acc0;
    sMt[j * 140 + r + 64] = acc1;
    if (r == 0) g_d[n0 + j] = acc2;
    __syncthreads();

    // pack B fragments (threads 0..127)
    if (tid < 128) {
        int s = tid >> 4, jj = (tid >> 2) & 3, q = tid & 3;
        int o0 = s * 16 + q * 2;
        float2 f0 = { sMt[jj * 140 + o0],     sMt[jj * 140 + o0 + 1] };
        float2 f1 = { sMt[jj * 140 + o0 + 8], sMt[jj * 140 + o0 + 9] };
        uint4 qv; uint32_t l0, l1;
        hilo(f0, qv.x, l0); hilo(f1, qv.y, l1);
        qv.z = l0; qv.w = l1;
        int Tg = b >> 1;
        g_bfr[(Tg * 8 + s) * 32 + (b & 1) * 16 + jj * 4 + q] = qv;
    }
}

// ================= kernel 2: main HMMA GEMM + fused epilogue =================
// out[m,n] = alpha[opt[m]] * ((x@M)[m,n] + d[n]) + c8[n]
// CTA tile 64m x 128n; grid (128, 2). 8 warps = 2(wm) x 4(wn).
static constexpr int MO_BFR = 0;        // uint4[16*8*32=4096] = 65536 B
static constexpr int MO_AH  = 65536;    // uint4[4*8*32=1024]  = 16384 B (A hi, lane-contiguous)
static constexpr int MO_AL  = 81920;    // uint4[1024]         = 16384 B (A lo)
static constexpr int MO_DS  = 98304;    // float[128]
static constexpr int MO_C8  = 98816;    // float[128]
static constexpr int MO_ALS = 99328;    // float[64]
static constexpr int MSMEM  = 99584;

__global__ __launch_bounds__(256) void main_hmma(const float* __restrict__ x,   // (8192,128)
                                                 const int* __restrict__ opt,   // (8192,)
                                                 float* __restrict__ out) {     // (8192,256)
    extern __shared__ __align__(16) char sm[];
    uint4* bfrs = (uint4*)(sm + MO_BFR);
    uint4* ah_s = (uint4*)(sm + MO_AH);
    uint4* al_s = (uint4*)(sm + MO_AL);
    float* ds   = (float*)(sm + MO_DS);
    float* c8s  = (float*)(sm + MO_C8);
    float* als  = (float*)(sm + MO_ALS);

    int tid = threadIdx.x;
    int m0 = blockIdx.x * 64;
    int nt = blockIdx.y, n0 = nt * 128;

    // stage B fragments (pure copy, L2-hot)
    #pragma unroll
    for (int i = 0; i < 16; i++)
        bfrs[tid + i * 256] = g_bfr[nt * 4096 + tid + i * 256];
    if (tid < 128) { ds[tid] = g_d[n0 + tid]; c8s[tid] = g_c8[n0 + tid]; }
    if (tid < 64)  als[tid] = g_alpha[opt[m0 + tid]];

    // stage A fragments (one conversion pass, hi/lo in separate arrays)
    #pragma unroll
    for (int i = 0; i < 4; i++) {
        int p = tid + i * 256;                 // 0..1023
        int lane_ = p & 31, s = (p >> 5) & 7, mf = p >> 8;   // mf = m16-frag 0..3
        int row = m0 + mf * 16 + (lane_ >> 2);
        int k0 = s * 16 + (lane_ & 3) * 2;
        const float* xr = x + (size_t)row * 128;
        float2 xa = *(const float2*)(xr + k0);
        float2 xb = *(const float2*)(xr + 8 * 128 + k0);
        float2 xc = *(const float2*)(xr + k0 + 8);
        float2 xd = *(const float2*)(xr + 8 * 128 + k0 + 8);
        uint4 hi, lo;
        hilo(xa, hi.x, lo.x); hilo(xb, hi.y, lo.y);
        hilo(xc, hi.z, lo.z); hilo(xd, hi.w, lo.w);
        ah_s[p] = hi;
        al_s[p] = lo;
    }
    __syncthreads();

    int wid = tid >> 5, lane = tid & 31;
    int wm = wid & 1, wn = wid >> 1;           // 2 x 4 warp grid
    float acc[2][4][4];
    #pragma unroll
    for (int a_ = 0; a_ < 2; a_++)
        #pragma unroll
        for (int b_ = 0; b_ < 4; b_++)
            #pragma unroll
            for (int c_ = 0; c_ < 4; c_++) acc[a_][b_][c_] = 0.f;

    #pragma unroll
    for (int s = 0; s < 8; s++) {
        uint4 ah[2], al[2];
        #pragma unroll
        for (int mt = 0; mt < 2; mt++) {
            int fp = ((wm * 2 + mt) * 8 + s) * 32 + lane;
            ah[mt] = ah_s[fp];
            al[mt] = al_s[fp];
        }
        #pragma unroll
        for (int t = 0; t < 4; t++) {
            uint4 bq = bfrs[((wn * 4 + t) * 8 + s) * 32 + lane];
            #pragma unroll
            for (int mt = 0; mt < 2; mt++) {
                mma16816(acc[mt][t], (const uint32_t*)&ah[mt], bq.x, bq.y);   // hi*hi
                mma16816(acc[mt][t], (const uint32_t*)&ah[mt], bq.z, bq.w);   // hi*lo
                mma16816(acc[mt][t], (const uint32_t*)&al[mt], bq.x, bq.y);   // lo*hi
            }
        }
    }

    // epilogue: out = alpha*(acc + d) + c8
    int g = lane >> 2, tq = lane & 3;
    #pragma unroll
    for (int mt = 0; mt < 2; mt++) {
        int rl = wm * 32 + mt * 16 + g;
        float a1 = als[rl], a2 = als[rl + 8];
        float* po1 = out + (size_t)(m0 + rl) * 256 + n0;
        float* po2 = po1 + 8 * 256;
        #pragma unroll
        for (int t = 0; t < 4; t++) {
            int nl = wn * 32 + t * 8 + tq * 2;
            float dn0 = ds[nl], dn1 = ds[nl + 1];
            float cn0 = c8s[nl], cn1 = c8s[nl + 1];
            float* c = acc[mt][t];
            float2 o1 = { fmaf(c[0] + dn0, a1, cn0), fmaf(c[1] + dn1, a1, cn1) };
            float2 o2 = { fmaf(c[2] + dn0, a2, cn0), fmaf(c[3] + dn1, a2, cn1) };
            *(float2*)(po1 + nl) = o1;
            *(float2*)(po2 + nl) = o2;
        }
    }
}

extern "C" void kernel_launch(void* const* d_in, const int* in_sizes, int n_in,
                              void* d_out, int out_size) {
    const float* x        = (const float*)d_in[0];   // (8192,128)
    const int*   option   = (const int*)  d_in[1];   // (8192,)
    const float* pre_fc_w = (const float*)d_in[2];   // (128,512)
    const float* pre_fc_b = (const float*)d_in[3];   // (512,)
    const float* value_w  = (const float*)d_in[4];   // (512,1024)
    const float* value_b  = (const float*)d_in[5];   // (1024,)
    const float* p_w      = (const float*)d_in[6];   // (16,64)
    const float* p_b      = (const float*)d_in[7];   // (64,)
    float* out = (float*)d_out;                      // (8192,256)

    cudaFuncSetAttribute(prep, cudaFuncAttributeMaxDynamicSharedMemorySize, P_SMEM);
    cudaFuncSetAttribute(main_hmma, cudaFuncAttributeMaxDynamicSharedMemorySize, MSMEM);

    prep<<<65, 256, P_SMEM>>>(pre_fc_w, pre_fc_b, value_w, p_w, p_b, value_b);
    main_hmma<<<dim3(128, 2), 256, MSMEM>>>(x, option, out);
}

// round 7
// speedup vs baseline: 1.8764x; 1.5261x over previous
#include <cuda_runtime.h>
#include <cuda_bf16.h>
#include <stdint.h>
#include <math.h>

// ---------------- global scratch (no allocations allowed) ----------------
// split-K partials: [ks=8][n=256][o stride 132] (o: 0..127 = M^T, 128 = d)
__device__ __align__(16) float g_part[8 * 256 * 132];
// B fragments: [Tg=32][s=8][lane=32] uint4 {b0_hi, b1_hi, b0_lo, b1_lo}
__device__ __align__(16) uint4 g_bfr[32 * 8 * 32];
__device__ __align__(16) float g_d[256];
__device__ __align__(16) float g_c8[256];
__device__ __align__(16) float g_alpha[16];

// ---------------- helpers ----------------
__device__ __forceinline__ void hilo(float2 f, uint32_t& h, uint32_t& l) {
    __nv_bfloat16 ax = __float2bfloat16(f.x), ay = __float2bfloat16(f.y);
    __nv_bfloat162 hv; hv.x = ax; hv.y = ay;
    float rx = f.x - __bfloat162float(ax);
    float ry = f.y - __bfloat162float(ay);
    __nv_bfloat162 lv = __floats2bfloat162_rn(rx, ry);
    h = *reinterpret_cast<uint32_t*>(&hv);
    l = *reinterpret_cast<uint32_t*>(&lv);
}

__device__ __forceinline__ void mma16816(float* c, const uint32_t* a, uint32_t b0, uint32_t b1) {
    asm volatile(
        "mma.sync.aligned.m16n8k16.row.col.f32.bf16.bf16.f32 "
        "{%0,%1,%2,%3}, {%4,%5,%6,%7}, {%8,%9}, {%0,%1,%2,%3};\n"
        : "+f"(c[0]), "+f"(c[1]), "+f"(c[2]), "+f"(c[3])
        : "r"(a[0]), "r"(a[1]), "r"(a[2]), "r"(a[3]), "r"(b0), "r"(b1));
}

// ================= kernel 1: split-K partial GEMM =================
// block b: nt = b&15 (16 n cols), ks = b>>4 (64 k). Computes partial
// M^T[n][o] = sum_{k-slab} foldW[k][n]*A_ext[o][k] into g_part[ks] (no atomics).
__global__ __launch_bounds__(256) void prep1(const float* __restrict__ A,     // pre_fc_w (128,512)
                                             const float* __restrict__ bias,  // pre_fc_b (512,)
                                             const float* __restrict__ vw) {  // value_w (512,1024)
    __shared__ __align__(16) float sA[129 * 68];   // [o][k], LD=68 (272B rows, 16B-aligned)
    __shared__ __align__(16) float sB[64 * 16];    // [k][n]
    int b = blockIdx.x, tid = threadIdx.x;
    int nt = b & 15, ks = b >> 4;
    int n0 = nt * 16, k0 = ks * 64;

    // stage A (129 x 64), float4
    #pragma unroll
    for (int i = 0; i < 9; i++) {
        int fid = tid + i * 256;
        if (fid < 129 * 16) {
            int row = fid >> 4, kq = fid & 15;
            float4 v = (row < 128) ? *(const float4*)(A + (size_t)row * 512 + k0 + kq * 4)
                                   : *(const float4*)(bias + k0 + kq * 4);
            *(float4*)(sA + row * 68 + kq * 4) = v;
        }
    }
    // stage foldW (64 k x 16 n)
    #pragma unroll
    for (int i = 0; i < 4; i++) {
        int idx = tid + i * 256;
        int k = idx >> 4, j = idx & 15;
        const float* p = vw + (size_t)(k0 + k) * 1024 + n0 + j;
        sB[k * 16 + j] = 0.25f * (p[0] + p[256] + p[512] + p[768]);
    }
    __syncthreads();

    int tx = tid & 3, ty = tid >> 2;   // tx: n quad, ty: 0..63 (o rows ty, ty+64; ty==0 also 128)
    float acc0[4] = {}, acc1[4] = {}, accb[4] = {};
    #pragma unroll 8
    for (int k = 0; k < 64; k++) {
        float4 b4 = *(const float4*)&sB[k * 16 + tx * 4];
        float a0 = sA[ty * 68 + k];
        float a1 = sA[(ty + 64) * 68 + k];
        acc0[0] = fmaf(a0, b4.x, acc0[0]); acc0[1] = fmaf(a0, b4.y, acc0[1]);
        acc0[2] = fmaf(a0, b4.z, acc0[2]); acc0[3] = fmaf(a0, b4.w, acc0[3]);
        acc1[0] = fmaf(a1, b4.x, acc1[0]); acc1[1] = fmaf(a1, b4.y, acc1[1]);
        acc1[2] = fmaf(a1, b4.z, acc1[2]); acc1[3] = fmaf(a1, b4.w, acc1[3]);
        if (ty == 0) {
            float ab = sA[128 * 68 + k];
            accb[0] = fmaf(ab, b4.x, accb[0]); accb[1] = fmaf(ab, b4.y, accb[1]);
            accb[2] = fmaf(ab, b4.z, accb[2]); accb[3] = fmaf(ab, b4.w, accb[3]);
        }
    }
    #pragma unroll
    for (int j = 0; j < 4; j++) {
        size_t base = ((size_t)ks * 256 + n0 + tx * 4 + j) * 132;
        g_part[base + ty]      = acc0[j];
        g_part[base + ty + 64] = acc1[j];
        if (ty == 0) g_part[base + 128] = accb[j];
    }
}

// ================= kernel 2: pack fragments + d + c8 + alpha =================
__global__ __launch_bounds__(256) void pack(const float* __restrict__ pw,   // p_w (16,64)
                                            const float* __restrict__ pb,   // p_b (64,)
                                            const float* __restrict__ vb) { // value_b (1024,)
    int b = blockIdx.x, tid = threadIdx.x;
    if (b < 32) {
        int p = b * 256 + tid;                 // == (Tg*8+s)*32+lane
        int lane = p & 31, s = (p >> 5) & 7;
        int n = (p >> 8) * 8 + (lane >> 2);
        int o0 = s * 16 + (lane & 3) * 2;
        float2 f0 = {0.f, 0.f}, f1 = {0.f, 0.f};
        #pragma unroll
        for (int ks = 0; ks < 8; ks++) {
            const float* q = &g_part[((size_t)ks * 256 + n) * 132];
            float2 u = *(const float2*)(q + o0);
            float2 v = *(const float2*)(q + o0 + 8);
            f0.x += u.x; f0.y += u.y; f1.x += v.x; f1.y += v.y;
        }
        uint4 qv; uint32_t l0, l1;
        hilo(f0, qv.x, l0); hilo(f1, qv.y, l1);
        qv.z = l0; qv.w = l1;
        g_bfr[p] = qv;
    } else {
        // d
        float d = 0.f;
        #pragma unroll
        for (int ks = 0; ks < 8; ks++)
            d += g_part[((size_t)ks * 256 + tid) * 132 + 128];
        g_d[tid] = d;
        // c8
        float c = 0.25f * (vb[tid] + vb[tid + 256] + vb[tid + 512] + vb[tid + 768]);
        g_c8[tid] = 0.125f * c;
        // alpha LUT
        __shared__ float s16[16 * 64];
        for (int i = tid; i < 16 * 64; i += 256) s16[i] = pw[i] + pb[i & 63];
        __syncthreads();
        if (tid < 16) {
            float* s = s16 + tid * 64;
            float S = 0.f;
            for (int t8 = 0; t8 < 8; t8++) {
                float bv = -1e30f; int bi = 0;
                for (int n = 0; n < 64; n++) {
                    float v = s[n];
                    if (v > bv) { bv = v; bi = n; }
                }
                S += 1.f / (1.f + expf(-bv));   // softmax([x,0])[0] = sigmoid(x)
                s[bi] = -1e30f;
            }
            g_alpha[tid] = S * (1.0f / 64.0f);
        }
    }
}

// ================= kernel 3: main HMMA GEMM + coalesced epilogue =================
// CTA tile 64m x 128n; grid (128, 2); 8 warps = 2(wm) x 4(wn); 3 CTAs/SM.
// B fragments streamed via LDG (L2-hot, no reuse), A fragments in smem,
// epilogue via smem transpose -> STG.128.
static constexpr int MO_AH  = 0;        // uint4[1024] = 16384 (A hi) ── overlaid with EPI
static constexpr int MO_AL  = 16384;    // uint4[1024] = 16384 (A lo) ──┘
static constexpr int MO_EPI = 0;        // float[64][132] = 33792 (post-mma scratch)
static constexpr int MO_DS  = 33792;    // float[128]
static constexpr int MO_C8  = 34304;    // float[128]
static constexpr int MO_ALS = 34816;    // float[64]
static constexpr int MSMEM  = 35072;

__global__ __launch_bounds__(256, 3) void main_hmma(const float* __restrict__ x,   // (8192,128)
                                                    const int* __restrict__ opt,   // (8192,)
                                                    float* __restrict__ out) {     // (8192,256)
    extern __shared__ __align__(16) char sm[];
    uint4* ah_s = (uint4*)(sm + MO_AH);
    uint4* al_s = (uint4*)(sm + MO_AL);
    float* epi  = (float*)(sm + MO_EPI);
    float* ds   = (float*)(sm + MO_DS);
    float* c8s  = (float*)(sm + MO_C8);
    float* als  = (float*)(sm + MO_ALS);

    int tid = threadIdx.x;
    int m0 = blockIdx.x * 64;
    int nt = blockIdx.y, n0 = nt * 128;

    if (tid < 128) { ds[tid] = g_d[n0 + tid]; c8s[tid] = g_c8[n0 + tid]; }
    if (tid < 64)  als[tid] = g_alpha[opt[m0 + tid]];

    // stage A fragments (hi/lo separate, lane-contiguous)
    #pragma unroll
    for (int i = 0; i < 4; i++) {
        int p = tid + i * 256;
        int lane_ = p & 31, s = (p >> 5) & 7, mf = p >> 8;
        int row = m0 + mf * 16 + (lane_ >> 2);
        int k0 = s * 16 + (lane_ & 3) * 2;
        const float* xr = x + (size_t)row * 128;
        float2 xa = *(const float2*)(xr + k0);
        float2 xb = *(const float2*)(xr + 8 * 128 + k0);
        float2 xc = *(const float2*)(xr + k0 + 8);
        float2 xd = *(const float2*)(xr + 8 * 128 + k0 + 8);
        uint4 hi, lo;
        hilo(xa, hi.x, lo.x); hilo(xb, hi.y, lo.y);
        hilo(xc, hi.z, lo.z); hilo(xd, hi.w, lo.w);
        ah_s[p] = hi;
        al_s[p] = lo;
    }
    __syncthreads();

    int wid = tid >> 5, lane = tid & 31;
    int wm = wid & 1, wn = wid >> 1;
    const uint4* bg = g_bfr + nt * 4096 + (wn * 4) * 256 + lane;  // t stride 256, s stride 32

    float acc[2][4][4];
    #pragma unroll
    for (int a_ = 0; a_ < 2; a_++)
        #pragma unroll
        for (int b_ = 0; b_ < 4; b_++)
            #pragma unroll
            for (int c_ = 0; c_ < 4; c_++) acc[a_][b_][c_] = 0.f;

    #pragma unroll
    for (int s = 0; s < 8; s++) {
        // B for all 4 t-tiles of this s: 4 independent LDG.128 (MLP=4)
        uint4 bq0 = bg[0 * 256 + s * 32];
        uint4 bq1 = bg[1 * 256 + s * 32];
        uint4 bq2 = bg[2 * 256 + s * 32];
        uint4 bq3 = bg[3 * 256 + s * 32];
        uint4 ah[2], al[2];
        #pragma unroll
        for (int mt = 0; mt < 2; mt++) {
            int fp = ((wm * 2 + mt) * 8 + s) * 32 + lane;
            ah[mt] = ah_s[fp];
            al[mt] = al_s[fp];
        }
        #pragma unroll
        for (int mt = 0; mt < 2; mt++) {
            mma16816(acc[mt][0], (const uint32_t*)&ah[mt], bq0.x, bq0.y);
            mma16816(acc[mt][0], (const uint32_t*)&ah[mt], bq0.z, bq0.w);
            mma16816(acc[mt][0], (const uint32_t*)&al[mt], bq0.x, bq0.y);
            mma16816(acc[mt][1], (const uint32_t*)&ah[mt], bq1.x, bq1.y);
            mma16816(acc[mt][1], (const uint32_t*)&ah[mt], bq1.z, bq1.w);
            mma16816(acc[mt][1], (const uint32_t*)&al[mt], bq1.x, bq1.y);
            mma16816(acc[mt][2], (const uint32_t*)&ah[mt], bq2.x, bq2.y);
            mma16816(acc[mt][2], (const uint32_t*)&ah[mt], bq2.z, bq2.w);
            mma16816(acc[mt][2], (const uint32_t*)&al[mt], bq2.x, bq2.y);
            mma16816(acc[mt][3], (const uint32_t*)&ah[mt], bq3.x, bq3.y);
            mma16816(acc[mt][3], (const uint32_t*)&ah[mt], bq3.z, bq3.w);
            mma16816(acc[mt][3], (const uint32_t*)&al[mt], bq3.x, bq3.y);
        }
    }

    // --- epilogue: raw accs -> smem (overwrites A frags), then coalesced read-back ---
    __syncthreads();
    int g = lane >> 2, tq = lane & 3;
    #pragma unroll
    for (int mt = 0; mt < 2; mt++) {
        int rl = wm * 32 + mt * 16 + g;
        #pragma unroll
        for (int t = 0; t < 4; t++) {
            int nl = wn * 32 + t * 8 + tq * 2;
            float* c = acc[mt][t];
            *(float2*)&epi[rl * 132 + nl]       = make_float2(c[0], c[1]);
            *(float2*)&epi[(rl + 8) * 132 + nl] = make_float2(c[2], c[3]);
        }
    }
    float4 dd = *(const float4*)&ds[lane * 4];
    float4 cc = *(const float4*)&c8s[lane * 4];
    __syncthreads();

    #pragma unroll
    for (int it = 0; it < 8; it++) {
        int row = wid * 8 + it;
        float a = als[row];
        float4 v = *(const float4*)&epi[row * 132 + lane * 4];
        float4 o;
        o.x = fmaf(v.x + dd.x, a, cc.x);
        o.y = fmaf(v.y + dd.y, a, cc.y);
        o.z = fmaf(v.z + dd.z, a, cc.z);
        o.w = fmaf(v.w + dd.w, a, cc.w);
        *(float4*)&out[(size_t)(m0 + row) * 256 + n0 + lane * 4] = o;
    }
}

extern "C" void kernel_launch(void* const* d_in, const int* in_sizes, int n_in,
                              void* d_out, int out_size) {
    const float* x        = (const float*)d_in[0];   // (8192,128)
    const int*   option   = (const int*)  d_in[1];   // (8192,)
    const float* pre_fc_w = (const float*)d_in[2];   // (128,512)
    const float* pre_fc_b = (const float*)d_in[3];   // (512,)
    const float* value_w  = (const float*)d_in[4];   // (512,1024)
    const float* value_b  = (const float*)d_in[5];   // (1024,)
    const float* p_w      = (const float*)d_in[6];   // (16,64)
    const float* p_b      = (const float*)d_in[7];   // (64,)
    float* out = (float*)d_out;                      // (8192,256)

    prep1<<<128, 256>>>(pre_fc_w, pre_fc_b, value_w);
    pack<<<33, 256>>>(p_w, p_b, value_b);
    main_hmma<<<dim3(128, 2), 256, MSMEM>>>(x, option, out);
}